// round 1
// baseline (speedup 1.0000x reference)
#include <cuda_runtime.h>
#include <math.h>

typedef unsigned long long u64;

#define Nn 8192
#define Dd 64

// ---------------- scratch (static device memory; no allocations) ----------------
__device__ float d_Cxy[(u64)Nn * Nn];
__device__ float d_Cyx[(u64)Nn * Nn];
__device__ float d_Cxx[(u64)Nn * Nn];
__device__ float d_Cyy[(u64)Nn * Nn];
__device__ float d_sqx[Nn], d_sqy[Nn];
__device__ float d_faa[Nn], d_gbb[Nn], d_gab[Nn], d_fba[Nn];
__device__ float d_tft[Nn], d_tgt[Nn], d_tftaa[Nn], d_tgtbb[Nn];

// ---------------- 0.5*||row||^2 ----------------
__global__ void sqnorm_kernel(const float* __restrict__ X, float* __restrict__ sq) {
    int gw   = (blockIdx.x * blockDim.x + threadIdx.x) >> 5;
    int lane = threadIdx.x & 31;
    if (gw >= Nn) return;
    const float* xr = X + (u64)gw * Dd;
    float a = xr[lane], b = xr[lane + 32];
    float s = a * a + b * b;
    #pragma unroll
    for (int o = 16; o; o >>= 1) s += __shfl_xor_sync(0xffffffffu, s, o);
    if (lane == 0) sq[gw] = 0.5f * s;
}

// ---------------- C[i][j] = max(0.5|a_i|^2 + 0.5|b_j|^2 - a_i.b_j, 0) ----------------
// 128x128 tile, 256 threads, 8x8 micro-tile per thread, K chunked by 32.
__global__ void __launch_bounds__(256, 2) cost_gemm_kernel(
    const float* __restrict__ A, const float* __restrict__ B,
    const float* __restrict__ sqa, const float* __restrict__ sqb,
    float* __restrict__ C)
{
    __shared__ float As[32][128];
    __shared__ float Bs[32][128];
    const int bi  = blockIdx.y * 128;
    const int bj  = blockIdx.x * 128;
    const int tid = threadIdx.x;
    const int tx  = tid & 15, ty = tid >> 4;

    float acc[8][8];
    #pragma unroll
    for (int r = 0; r < 8; ++r)
        #pragma unroll
        for (int c = 0; c < 8; ++c) acc[r][c] = 0.f;

    for (int kc = 0; kc < Dd; kc += 32) {
        #pragma unroll
        for (int it = 0; it < 4; ++it) {
            int idx = tid + it * 256;          // 0..1023 float4 slots (128 rows x 8 f4)
            int row = idx >> 3;
            int kq  = idx & 7;
            float4 a = *(const float4*)(A + (u64)(bi + row) * Dd + kc + kq * 4);
            float4 b = *(const float4*)(B + (u64)(bj + row) * Dd + kc + kq * 4);
            As[kq * 4 + 0][row] = a.x; As[kq * 4 + 1][row] = a.y;
            As[kq * 4 + 2][row] = a.z; As[kq * 4 + 3][row] = a.w;
            Bs[kq * 4 + 0][row] = b.x; Bs[kq * 4 + 1][row] = b.y;
            Bs[kq * 4 + 2][row] = b.z; Bs[kq * 4 + 3][row] = b.w;
        }
        __syncthreads();
        #pragma unroll
        for (int k = 0; k < 32; ++k) {
            float4 a0 = *(const float4*)&As[k][ty * 4];
            float4 a1 = *(const float4*)&As[k][64 + ty * 4];
            float4 b0 = *(const float4*)&Bs[k][tx * 4];
            float4 b1 = *(const float4*)&Bs[k][64 + tx * 4];
            float av[8] = {a0.x, a0.y, a0.z, a0.w, a1.x, a1.y, a1.z, a1.w};
            float bv[8] = {b0.x, b0.y, b0.z, b0.w, b1.x, b1.y, b1.z, b1.w};
            #pragma unroll
            for (int r = 0; r < 8; ++r)
                #pragma unroll
                for (int c = 0; c < 8; ++c)
                    acc[r][c] = fmaf(av[r], bv[c], acc[r][c]);
        }
        __syncthreads();
    }

    #pragma unroll
    for (int rg = 0; rg < 2; ++rg)
        #pragma unroll
        for (int q = 0; q < 4; ++q) {
            int i = bi + rg * 64 + ty * 4 + q;
            float sa = sqa[i];
            int r = rg * 4 + q;
            #pragma unroll
            for (int cg = 0; cg < 2; ++cg) {
                int j0 = bj + cg * 64 + tx * 4;
                float4 v;
                v.x = fmaxf(sa + sqb[j0 + 0] - acc[r][cg * 4 + 0], 0.f);
                v.y = fmaxf(sa + sqb[j0 + 1] - acc[r][cg * 4 + 1], 0.f);
                v.z = fmaxf(sa + sqb[j0 + 2] - acc[r][cg * 4 + 2], 0.f);
                v.w = fmaxf(sa + sqb[j0 + 3] - acc[r][cg * 4 + 3], 0.f);
                *(float4*)(C + (u64)i * Nn + j0) = v;
            }
        }
}

// ---------------- transpose Cxy -> Cyx ----------------
__global__ void transpose_kernel(const float* __restrict__ in, float* __restrict__ out) {
    __shared__ float tile[32][33];
    int x  = blockIdx.x * 32 + threadIdx.x;
    int y0 = blockIdx.y * 32;
    #pragma unroll
    for (int r = threadIdx.y; r < 32; r += 8)
        tile[r][threadIdx.x] = in[(u64)(y0 + r) * Nn + x];
    __syncthreads();
    int x2 = blockIdx.y * 32 + threadIdx.x;
    int y2 = blockIdx.x * 32;
    #pragma unroll
    for (int r = threadIdx.y; r < 32; r += 8)
        out[(u64)(y2 + r) * Nn + x2] = tile[threadIdx.x][r];
}

// ---------------- softmin: out[i] = -eps * LSE_j( base + (pot[j]-C[i,j])/eps ) ----------------
// One row per block, 256 threads, 32 elements/thread, two passes (max, then exp-sum;
// 2nd pass re-reads the 32KB row from L2).
__global__ void __launch_bounds__(256) softmin_kernel(
    const float* __restrict__ C, const float* __restrict__ pot,
    const float* __restrict__ eps_ptr, float base_log, float* __restrict__ out)
{
    __shared__ float redA[8];
    __shared__ float redB[8];
    const int tid = threadIdx.x, lane = tid & 31, wid = tid >> 5;
    const float eps = *eps_ptr;
    const float inv_eps = 1.0f / eps;
    const int row = blockIdx.x;
    const float* Cr = C + (u64)row * Nn;

    // pass 1: max
    float m = -3.4e38f;
    #pragma unroll
    for (int c = 0; c < 8; ++c) {
        int j = (c << 10) + (tid << 2);
        float4 cc = *(const float4*)(Cr + j);
        float v0, v1, v2, v3;
        if (pot) {
            float4 p = *(const float4*)(pot + j);
            v0 = fmaf(p.x - cc.x, inv_eps, base_log);
            v1 = fmaf(p.y - cc.y, inv_eps, base_log);
            v2 = fmaf(p.z - cc.z, inv_eps, base_log);
            v3 = fmaf(p.w - cc.w, inv_eps, base_log);
        } else {
            v0 = fmaf(cc.x, -inv_eps, base_log);
            v1 = fmaf(cc.y, -inv_eps, base_log);
            v2 = fmaf(cc.z, -inv_eps, base_log);
            v3 = fmaf(cc.w, -inv_eps, base_log);
        }
        m = fmaxf(m, fmaxf(fmaxf(v0, v1), fmaxf(v2, v3)));
    }
    #pragma unroll
    for (int o = 16; o; o >>= 1) m = fmaxf(m, __shfl_xor_sync(0xffffffffu, m, o));
    if (lane == 0) redA[wid] = m;
    __syncthreads();
    if (tid == 0) {
        float mm = redA[0];
        #pragma unroll
        for (int i = 1; i < 8; ++i) mm = fmaxf(mm, redA[i]);
        redA[0] = mm;
    }
    __syncthreads();
    const float M = redA[0];

    // pass 2: sum of exp(v - M)
    float s = 0.f;
    #pragma unroll
    for (int c = 0; c < 8; ++c) {
        int j = (c << 10) + (tid << 2);
        float4 cc = *(const float4*)(Cr + j);
        float v0, v1, v2, v3;
        if (pot) {
            float4 p = *(const float4*)(pot + j);
            v0 = fmaf(p.x - cc.x, inv_eps, base_log);
            v1 = fmaf(p.y - cc.y, inv_eps, base_log);
            v2 = fmaf(p.z - cc.z, inv_eps, base_log);
            v3 = fmaf(p.w - cc.w, inv_eps, base_log);
        } else {
            v0 = fmaf(cc.x, -inv_eps, base_log);
            v1 = fmaf(cc.y, -inv_eps, base_log);
            v2 = fmaf(cc.z, -inv_eps, base_log);
            v3 = fmaf(cc.w, -inv_eps, base_log);
        }
        s += __expf(v0 - M);
        s += __expf(v1 - M);
        s += __expf(v2 - M);
        s += __expf(v3 - M);
    }
    #pragma unroll
    for (int o = 16; o; o >>= 1) s += __shfl_xor_sync(0xffffffffu, s, o);
    if (lane == 0) redB[wid] = s;
    __syncthreads();
    if (tid == 0) {
        float S = 0.f;
        #pragma unroll
        for (int i = 0; i < 8; ++i) S += redB[i];
        out[row] = -eps * (logf(S) + M);
    }
}

// ---------------- symmetrized dual update ----------------
__global__ void update_kernel(const float* __restrict__ tftaa, const float* __restrict__ tgtbb,
                              const float* __restrict__ tgt, const float* __restrict__ tft,
                              float* __restrict__ faa, float* __restrict__ gbb,
                              float* __restrict__ gab, float* __restrict__ fba)
{
    int i = blockIdx.x * blockDim.x + threadIdx.x;
    faa[i] = 0.5f * (faa[i] + tftaa[i]);
    gbb[i] = 0.5f * (gbb[i] + tgtbb[i]);
    gab[i] = 0.5f * (gab[i] + tgt[i]);
    fba[i] = 0.5f * (fba[i] + tft[i]);
}

// ---------------- final scalar ----------------
__global__ void final_kernel(const float* __restrict__ fbaf, const float* __restrict__ faaf,
                             const float* __restrict__ gabf, const float* __restrict__ gbbf,
                             float* __restrict__ out)
{
    __shared__ float red[32];
    int tid = threadIdx.x;      // 1024 threads
    int lane = tid & 31, wid = tid >> 5;
    float s = 0.f;
    for (int i = tid; i < Nn; i += 1024)
        s += (fbaf[i] - faaf[i]) + (gabf[i] - gbbf[i]);
    #pragma unroll
    for (int o = 16; o; o >>= 1) s += __shfl_xor_sync(0xffffffffu, s, o);
    if (lane == 0) red[wid] = s;
    __syncthreads();
    if (wid == 0) {
        float v = red[lane];
        #pragma unroll
        for (int o = 16; o; o >>= 1) v += __shfl_xor_sync(0xffffffffu, v, o);
        if (lane == 0) out[0] = v / (float)Nn;
    }
}

// ---------------- launch ----------------
extern "C" void kernel_launch(void* const* d_in, const int* in_sizes, int n_in,
                              void* d_out, int out_size)
{
    const float* X   = (const float*)d_in[0];   // g [8192,64]
    const float* Y   = (const float*)d_in[1];   // Y [8192,64]
    const float* eps = (const float*)d_in[2];   // eps_list
    const int n_eps  = in_sizes[2];
    float* out = (float*)d_out;

    float *Cxy, *Cyx, *Cxx, *Cyy, *sqx, *sqy;
    float *faa, *gbb, *gab, *fba, *tft, *tgt, *tftaa, *tgtbb;
    cudaGetSymbolAddress((void**)&Cxy, d_Cxy);
    cudaGetSymbolAddress((void**)&Cyx, d_Cyx);
    cudaGetSymbolAddress((void**)&Cxx, d_Cxx);
    cudaGetSymbolAddress((void**)&Cyy, d_Cyy);
    cudaGetSymbolAddress((void**)&sqx, d_sqx);
    cudaGetSymbolAddress((void**)&sqy, d_sqy);
    cudaGetSymbolAddress((void**)&faa, d_faa);
    cudaGetSymbolAddress((void**)&gbb, d_gbb);
    cudaGetSymbolAddress((void**)&gab, d_gab);
    cudaGetSymbolAddress((void**)&fba, d_fba);
    cudaGetSymbolAddress((void**)&tft, d_tft);
    cudaGetSymbolAddress((void**)&tgt, d_tgt);
    cudaGetSymbolAddress((void**)&tftaa, d_tftaa);
    cudaGetSymbolAddress((void**)&tgtbb, d_tgtbb);

    const float LOGW = -logf((float)Nn);   // a_log == b_log (uniform, N == M)

    // costs
    sqnorm_kernel<<<1024, 256>>>(X, sqx);
    sqnorm_kernel<<<1024, 256>>>(Y, sqy);
    dim3 gg(Nn / 128, Nn / 128);
    cost_gemm_kernel<<<gg, 256>>>(X, Y, sqx, sqy, Cxy);
    cost_gemm_kernel<<<gg, 256>>>(X, X, sqx, sqx, Cxx);
    cost_gemm_kernel<<<gg, 256>>>(Y, Y, sqy, sqy, Cyy);
    transpose_kernel<<<dim3(Nn / 32, Nn / 32), dim3(32, 8)>>>(Cxy, Cyx);

    // init at eps0
    softmin_kernel<<<Nn, 256>>>(Cxx, nullptr, eps, LOGW, faa);
    softmin_kernel<<<Nn, 256>>>(Cyy, nullptr, eps, LOGW, gbb);
    softmin_kernel<<<Nn, 256>>>(Cyx, nullptr, eps, LOGW, gab);
    softmin_kernel<<<Nn, 256>>>(Cxy, nullptr, eps, LOGW, fba);

    // annealed symmetric Sinkhorn scan
    for (int k = 0; k < n_eps; ++k) {
        const float* ek = eps + k;
        softmin_kernel<<<Nn, 256>>>(Cxy, gab, ek, LOGW, tft);
        softmin_kernel<<<Nn, 256>>>(Cyx, fba, ek, LOGW, tgt);
        softmin_kernel<<<Nn, 256>>>(Cxx, faa, ek, LOGW, tftaa);
        softmin_kernel<<<Nn, 256>>>(Cyy, gbb, ek, LOGW, tgtbb);
        update_kernel<<<Nn / 256, 256>>>(tftaa, tgtbb, tgt, tft, faa, gbb, gab, fba);
    }

    // final extrapolation at eps = blur^p
    const float* el = eps + (n_eps - 1);
    softmin_kernel<<<Nn, 256>>>(Cxy, gab, el, LOGW, tft);    // f_ba_f
    softmin_kernel<<<Nn, 256>>>(Cyx, fba, el, LOGW, tgt);    // g_ab_f
    softmin_kernel<<<Nn, 256>>>(Cxx, faa, el, LOGW, tftaa);  // f_aa_f
    softmin_kernel<<<Nn, 256>>>(Cyy, gbb, el, LOGW, tgtbb);  // g_bb_f

    final_kernel<<<1, 1024>>>(tft, tftaa, tgt, tgtbb, out);
}